// round 15
// baseline (speedup 1.0000x reference)
#include <cuda_runtime.h>
#include <cuda_bf16.h>
#include <math.h>
#include <stdint.h>

typedef uint32_t u32;

#define NBLK 128
#define NTHR 512
#define BB   32
#define CC   1024
#define C2   2048
#define TT   1024
#define WS   2056   // weight row stride (bf16 elems): conflict-free LDSM

// SMEM byte layout: weights | 2x16KB act buffers | mbarriers
#define OFF_BUF_BYTES (48*WS*2)              // 197376 (128B aligned)
#define BUFSZ 16384
#define OFF_MBAR (OFF_BUF_BYTES + 2*BUFSZ)   // 230144
#define SMEM_BYTES (OFF_MBAR + 64)           // 230208

// GMEM staging (chunk-major, swizzled, [hi 8KB | lo 8KB] per 16KB chunk)
__device__ __align__(128) unsigned char g_xs[134217728]; // [t][8 chunks][16KB]
__device__ __align__(128) unsigned char g_hs[131072];    // [8 chunks][16KB]
__device__ __align__(128) unsigned char g_ys[262144];    // [16 chunks][16KB]
__device__ float g_y2[BB*CC];

// dataflow counters (padded to 128B lines) + hierarchical barrier state
__device__ unsigned g_ycnt[16*32];
__device__ unsigned g_hcnt[4*32];
__device__ unsigned g_c1[8*32];
__device__ unsigned g_c2;
__device__ volatile unsigned g_gen;

__device__ __forceinline__ float geluf(float u) {
    return 0.5f * u * (1.0f + erff(u * 0.70710678118654752440f));
}

// two-level grid barrier: 8 group counters (16 CTAs each) -> 1 master (8 groups)
__device__ __forceinline__ void gbar(int cta) {
    __syncthreads();
    if (threadIdx.x == 0) {
        __threadfence();
        unsigned gen = g_gen;
        unsigned o = atomicAdd(&g_c1[(cta & 7) * 32], 1u);
        if ((o & 15u) == 15u) {
            unsigned o2 = atomicAdd(&g_c2, 1u);
            if ((o2 & 7u) == 7u) {
                __threadfence();
                g_gen = gen + 1u;
            } else {
                while (g_gen == gen) {}
            }
        } else {
            while (g_gen == gen) {}
        }
        __threadfence();
    }
    __syncthreads();
}

__device__ __forceinline__ void waitcnt(const unsigned* c, unsigned tgt) {
    while (*(volatile const unsigned*)c < tgt) {}
    __threadfence();
}

__device__ __forceinline__ void ldsm4(u32 (&r)[4], u32 addr) {
    asm volatile("ldmatrix.sync.aligned.m8n8.x4.shared.b16 {%0,%1,%2,%3}, [%4];"
        : "=r"(r[0]), "=r"(r[1]), "=r"(r[2]), "=r"(r[3]) : "r"(addr));
}
__device__ __forceinline__ void ldsm2(u32 (&r)[2], u32 addr) {
    asm volatile("ldmatrix.sync.aligned.m8n8.x2.shared.b16 {%0,%1}, [%2];"
        : "=r"(r[0]), "=r"(r[1]) : "r"(addr));
}
__device__ __forceinline__ void mma16816(float (&c)[4], const u32 (&a)[4], const u32 (&b)[2]) {
    asm volatile("mma.sync.aligned.m16n8k16.row.col.f32.bf16.bf16.f32 "
        "{%0,%1,%2,%3}, {%4,%5,%6,%7}, {%8,%9}, {%0,%1,%2,%3};"
        : "+f"(c[0]), "+f"(c[1]), "+f"(c[2]), "+f"(c[3])
        : "r"(a[0]), "r"(a[1]), "r"(a[2]), "r"(a[3]), "r"(b[0]), "r"(b[1]));
}

__device__ __forceinline__ void mbar_init(u32 a, u32 cnt) {
    asm volatile("mbarrier.init.shared.b64 [%0], %1;" :: "r"(a), "r"(cnt) : "memory");
}
__device__ __forceinline__ void mbar_arrive(u32 a) {
    asm volatile("mbarrier.arrive.shared.b64 _, [%0];" :: "r"(a) : "memory");
}
__device__ __forceinline__ void mbar_expect_tx(u32 a, u32 n) {
    asm volatile("mbarrier.arrive.expect_tx.shared.b64 _, [%0], %1;" :: "r"(a), "r"(n) : "memory");
}
__device__ __forceinline__ void mbar_wait(u32 a, u32 ph) {
    u32 done;
    asm volatile("{\n\t.reg .pred p;\n\t"
        "mbarrier.try_wait.parity.acquire.cta.shared::cta.b64 p, [%1], %2;\n\t"
        "selp.b32 %0, 1, 0, p;\n\t}"
        : "=r"(done) : "r"(a), "r"(ph) : "memory");
    if (!done) {
        asm volatile("{\n\t.reg .pred P1;\n\t"
            "WAIT_LOOP_%=:\n\t"
            "mbarrier.try_wait.parity.acquire.cta.shared::cta.b64 P1, [%0], %1, 0x989680;\n\t"
            "@P1 bra.uni WAIT_DONE_%=;\n\t"
            "bra.uni WAIT_LOOP_%=;\n\t"
            "WAIT_DONE_%=:\n\t}"
            :: "r"(a), "r"(ph) : "memory");
    }
}
__device__ __forceinline__ void bulk_cp(u32 dst, const void* src, u32 bytes, u32 mbar) {
    asm volatile("cp.async.bulk.shared::cluster.global.mbarrier::complete_tx::bytes "
        "[%0], [%1], %2, [%3];" :: "r"(dst), "l"(src), "r"(bytes), "r"(mbar) : "memory");
}
__device__ __forceinline__ void fence_async() {
    asm volatile("fence.proxy.async.shared::cta;" ::: "memory");
}

__device__ __forceinline__ void split2(float v, __nv_bfloat16& h, __nv_bfloat16& l) {
    h = __float2bfloat16_rn(v);
    l = __float2bfloat16_rn(v - __bfloat162float(h));
}
__device__ __forceinline__ u32 packhl(__nv_bfloat16 a, __nv_bfloat16 b) {
    __nv_bfloat162 p = {a, b};
    return *(u32*)&p;
}

// swizzled byte offset within an 8KB plane (32 rows x 128 bf16 cols)
__device__ __forceinline__ u32 swz(u32 r, u32 c) {
    u32 b = (((r >> 3) + ((c >> 6) << 2)) << 10) + ((r & 7) << 7) + ((c & 63) << 1);
    return b ^ ((b >> 3) & 0x70);
}

__global__ void __launch_bounds__(NTHR, 1)
rnn_kernel(const float* __restrict__ x,   const float* __restrict__ Wa,
           const float* __restrict__ ba,  const float* __restrict__ Wb,
           const float* __restrict__ bbv, const float* __restrict__ gamma,
           const float* __restrict__ beta, float* __restrict__ out)
{
    extern __shared__ unsigned char smb[];
    __nv_bfloat16* sWaHi = (__nv_bfloat16*)(smb);
    __nv_bfloat16* sWaLo = (__nv_bfloat16*)(smb + 16*WS*2);
    __nv_bfloat16* sWbHi = (__nv_bfloat16*)(smb + 32*WS*2);
    __nv_bfloat16* sWbLo = (__nv_bfloat16*)(smb + 40*WS*2);
    float* sRed = (float*)(smb + OFF_BUF_BYTES);   // aliases buf0; epilogue-only

    const int tid = threadIdx.x;
    const int cta = blockIdx.x;
    const int lane = tid & 31, wid = tid >> 5;

    const u32 smemBase = (u32)__cvta_generic_to_shared(smb);
    const u32 mbFull[2]  = {smemBase + OFF_MBAR,      smemBase + OFF_MBAR + 8};
    const u32 mbEmpty[2] = {smemBase + OFF_MBAR + 16, smemBase + OFF_MBAR + 24};
    const u32 bufB[2]    = {smemBase + OFF_BUF_BYTES, smemBase + OFF_BUF_BYTES + BUFSZ};

    if (tid == 0) {
        mbar_init(mbFull[0], 1);  mbar_init(mbFull[1], 1);
        mbar_init(mbEmpty[0], 16); mbar_init(mbEmpty[1], 16);
    }
    // reset dataflow counters (ordered by init gbar below; replay-safe)
    if (cta == 0) {
        if (tid < 16) g_ycnt[tid*32] = 0u;
        if (tid < 4)  g_hcnt[tid*32] = 0u;
    }

    // ---- one-time: weights -> smem bf16 hi/lo planes ----
    for (int idx = tid; idx < 16*C2; idx += NTHR) {
        int r = idx >> 11, k = idx & (C2-1);
        float v = Wa[(size_t)(cta*16 + r)*C2 + k];
        split2(v, sWaHi[r*WS + k], sWaLo[r*WS + k]);
    }
    for (int idx = tid; idx < 8*C2; idx += NTHR) {
        int r = idx >> 11, k = idx & (C2-1);
        float v = Wb[(size_t)(cta*8 + r)*C2 + k];
        split2(v, sWbHi[r*WS + k], sWbLo[r*WS + k]);
    }
    // ---- one-time: x -> chunk-major swizzled hi/lo (this CTA owns 8 t values) ----
    for (int tt = cta*8; tt < cta*8 + 8; ++tt) {
        for (int p = tid; p < 32*512; p += NTHR) {
            int b = p >> 9, c0 = (p & 511) << 1;
            float2 v = *(const float2*)(x + ((size_t)b*TT + tt)*CC + c0);
            __nv_bfloat16 h0,l0,h1,l1;
            split2(v.x, h0, l0);
            split2(v.y, h1, l1);
            unsigned char* base = g_xs + ((size_t)tt*8 + (c0 >> 7))*BUFSZ;
            u32 off = swz((u32)b, (u32)(c0 & 127));
            *(u32*)(base + off)        = packhl(h0, h1);
            *(u32*)(base + 8192 + off) = packhl(l0, l1);
        }
    }
    // ---- h0 = 0 ----
    {
        int g = cta*NTHR + tid;
        if (g < 32768) ((u32*)g_hs)[g] = 0u;
    }
    gbar(cta);

    // ---- warp roles ----
    const int kspA = wid & 3, nt = wid >> 2;   // A: 4 n-tiles(8b) x 4-way k-split
    const int mtB = wid & 1, kspB = wid >> 1;  // B: 2 m-tiles(16b) x 8-way k-split
    const int myB = cta >> 2, myQ = cta & 3;

    const int aRow = lane & 15, aKh = (lane >> 4) * 8;
    const int bRow = lane & 7,  bKh = ((lane >> 3) & 1) * 8;
    const u32 waHi = smemBase + 0        + (aRow*WS + aKh)*2;
    const u32 waLo = smemBase + 16*WS*2  + (aRow*WS + aKh)*2;
    const u32 wbHi = smemBase + 32*WS*2  + (bRow*WS + bKh)*2;
    const u32 wbLo = smemBase + 40*WS*2  + (bRow*WS + bKh)*2;

    u32 aAct[2][2], bAct[2];
    #pragma unroll
    for (int s = 0; s < 2; ++s) {
        #pragma unroll
        for (int u = 0; u < 2; ++u)
            aAct[s][u] = bufB[s] + swz((u32)(nt*8 + (lane & 7)),
                                       (u32)(32*kspA + 16*u + ((lane >> 3) & 1)*8));
        bAct[s] = bufB[s] + swz((u32)(mtB*16 + (lane & 15)),
                                (u32)(16*kspB + ((lane >> 4) & 1)*8));
    }

    int cPh[2] = {0, 0};
    int pPh[2] = {0, 0};
    int pFirst[2] = {1, 1};

    for (int t = 0; t < TT; ++t) {
        // ===== Phase A: y = gelu([h,x_t] @ Wa^T + ba); x chunks first, then gated h =====
        float c0a[4] = {0,0,0,0}, c1a[4] = {0,0,0,0}, c2a[4] = {0,0,0,0};
        {
            auto stageA = [&](int ch) {
                int s = ch & 1;
                if (pFirst[s]) pFirst[s] = 0;
                else { mbar_wait(mbEmpty[s], pPh[s]); pPh[s] ^= 1; }
                const void* src;
                if (ch < 8) {
                    src = g_xs + ((size_t)t*8 + ch)*BUFSZ;
                } else {
                    waitcnt(&g_hcnt[((ch - 8) >> 1)*32], 32u*(unsigned)t);
                    src = g_hs + (size_t)(ch - 8)*BUFSZ;
                }
                mbar_expect_tx(mbFull[s], BUFSZ);
                bulk_cp(bufB[s], src, BUFSZ, mbFull[s]);
            };
            if (tid == 0) { fence_async(); stageA(0); stageA(1); }
            #pragma unroll 2
            for (int ch = 0; ch < 16; ++ch) {
                const int s = ch & 1;
                const int kw = (ch < 8 ? ch + 8 : ch - 8) * 128;
                mbar_wait(mbFull[s], cPh[s]); cPh[s] ^= 1;
                #pragma unroll
                for (int u = 0; u < 2; ++u) {
                    const int kb = kw + 32*kspA + 16*u;
                    u32 Ah[4], Al[4], Bh[2], Bl[2];
                    ldsm4(Ah, waHi + kb*2);
                    ldsm4(Al, waLo + kb*2);
                    ldsm2(Bh, aAct[s][u]);
                    ldsm2(Bl, aAct[s][u] + 8192);
                    mma16816(c0a, Ah, Bh);
                    mma16816(c1a, Ah, Bl);
                    mma16816(c2a, Al, Bh);
                }
                __syncwarp();
                if (lane == 0) mbar_arrive(mbEmpty[s]);
                if (tid == 0 && ch < 14) stageA(ch + 2);
            }
        }
        {   // A epilogue: partials -> sRed[kspA][16j][32b] (stride 34)
            __syncthreads();   // all warps done reading buffers before sRed (aliases buf0)
            const int r0 = lane >> 2, cb = nt*8 + 2*(lane & 3);
            *(float2*)(sRed + (kspA*16 + r0    )*34 + cb) = make_float2(c0a[0]+c1a[0]+c2a[0], c0a[1]+c1a[1]+c2a[1]);
            *(float2*)(sRed + (kspA*16 + r0 + 8)*34 + cb) = make_float2(c0a[2]+c1a[2]+c2a[2], c0a[3]+c1a[3]+c2a[3]);
            __syncthreads();
            if (tid < 256) {
                const int b = tid >> 3, j2 = (tid & 7)*2;
                const int jg0 = cta*16 + j2;
                float v0 = sRed[j2*34 + b] + sRed[(16 + j2)*34 + b]
                         + sRed[(32 + j2)*34 + b] + sRed[(48 + j2)*34 + b];
                float v1 = sRed[(j2+1)*34 + b] + sRed[(16 + j2+1)*34 + b]
                         + sRed[(32 + j2+1)*34 + b] + sRed[(48 + j2+1)*34 + b];
                float y0 = geluf(v0 + __ldg(ba + jg0));
                float y1 = geluf(v1 + __ldg(ba + jg0 + 1));
                __nv_bfloat16 h0,l0,h1,l1;
                split2(y0, h0, l0);
                split2(y1, h1, l1);
                unsigned char* base = g_ys + (size_t)(jg0 >> 7)*BUFSZ;
                u32 off = swz((u32)b, (u32)(jg0 & 127));
                *(u32*)(base + off)        = packhl(h0, h1);
                *(u32*)(base + 8192 + off) = packhl(l0, l1);
            }
            __syncthreads();
            if (tid == 0) {
                __threadfence();
                atomicAdd(&g_ycnt[(cta >> 3)*32], 1u);
            }
        }
        // no grid barrier: B gated per-chunk by g_ycnt

        // ===== Phase B: y2 = y @ Wb^T + bb =====
        float d0[4] = {0,0,0,0}, d1[4] = {0,0,0,0}, d2[4] = {0,0,0,0};
        {
            auto stageB = [&](int ch) {
                int s = ch & 1;
                mbar_wait(mbEmpty[s], pPh[s]); pPh[s] ^= 1;
                waitcnt(&g_ycnt[ch*32], 8u*(unsigned)(t + 1));
                mbar_expect_tx(mbFull[s], BUFSZ);
                bulk_cp(bufB[s], g_ys + (size_t)ch*BUFSZ, BUFSZ, mbFull[s]);
            };
            if (tid == 0) { fence_async(); stageB(0); stageB(1); }
            #pragma unroll 2
            for (int ch = 0; ch < 16; ++ch) {
                const int s = ch & 1;
                mbar_wait(mbFull[s], cPh[s]); cPh[s] ^= 1;
                {
                    const int kb = ch*128 + 16*kspB;
                    u32 Ah[4], Al[4], Bh[2], Bl[2];
                    ldsm4(Ah, bAct[s]);
                    ldsm4(Al, bAct[s] + 8192);
                    ldsm2(Bh, wbHi + kb*2);
                    ldsm2(Bl, wbLo + kb*2);
                    mma16816(d0, Ah, Bh);
                    mma16816(d1, Ah, Bl);
                    mma16816(d2, Al, Bh);
                }
                __syncwarp();
                if (lane == 0) mbar_arrive(mbEmpty[s]);
                if (tid == 0 && ch < 14) stageB(ch + 2);
            }
        }
        {   // B epilogue: partials -> sRed[kspB][32b][8j] (stride 10)
            __syncthreads();
            const int r0 = mtB*16 + (lane >> 2), cb = 2*(lane & 3);
            *(float2*)(sRed + (kspB*32 + r0    )*10 + cb) = make_float2(d0[0]+d1[0]+d2[0], d0[1]+d1[1]+d2[1]);
            *(float2*)(sRed + (kspB*32 + r0 + 8)*10 + cb) = make_float2(d0[2]+d1[2]+d2[2], d0[3]+d1[3]+d2[3]);
            __syncthreads();
            if (tid < 256) {
                const int b = tid >> 3, j = tid & 7;
                float v = 0.f;
                #pragma unroll
                for (int p = 0; p < 8; ++p) v += sRed[(p*32 + b)*10 + j];
                const int jg = cta*8 + j;
                v += __ldg(bbv + jg);
                __stcg(&g_y2[(size_t)b*CC + jg], v);
            }
        }
        gbar(cta);   // the single full barrier: LN needs all y2 columns

        // ===== Phase C: h = LN(y2)+y2 =====
        {
            float s = 0.f, sq = 0.f;
            #pragma unroll
            for (int i = tid; i < CC; i += NTHR) {
                float v = __ldcg(g_y2 + (size_t)myB*CC + i);
                s += v; sq += v*v;
            }
            #pragma unroll
            for (int o = 16; o; o >>= 1) {
                s  += __shfl_xor_sync(0xffffffffu, s,  o);
                sq += __shfl_xor_sync(0xffffffffu, sq, o);
            }
            if (lane == 0) { sRed[wid] = s; sRed[16 + wid] = sq; }
            __syncthreads();
            if (tid < 128) {
                float S = 0.f, Q = 0.f;
                #pragma unroll
                for (int w = 0; w < 16; ++w) { S += sRed[w]; Q += sRed[16 + w]; }
                float mu  = S * (1.0f / CC);
                float var = Q * (1.0f / CC) - mu * mu;
                float r   = rsqrtf(var + 1e-5f);
                int c0 = myQ * 256 + tid*2;
                float v0 = __ldcg(g_y2 + (size_t)myB*CC + c0);
                float v1 = __ldcg(g_y2 + (size_t)myB*CC + c0 + 1);
                float hn0 = (v0 - mu) * r * __ldg(gamma + c0)     + __ldg(beta + c0)     + v0;
                float hn1 = (v1 - mu) * r * __ldg(gamma + c0 + 1) + __ldg(beta + c0 + 1) + v1;
                *(float2*)(out + (size_t)myB*TT*CC + (size_t)t*CC + c0) = make_float2(hn0, hn1);
                __nv_bfloat16 h0,l0,h1,l1;
                split2(hn0, h0, l0);
                split2(hn1, h1, l1);
                unsigned char* base = g_hs + (size_t)(c0 >> 7)*BUFSZ;
                u32 off = swz((u32)myB, (u32)(c0 & 127));
                *(u32*)(base + off)        = packhl(h0, h1);
                *(u32*)(base + 8192 + off) = packhl(l0, l1);
            }
            __syncthreads();   // h writes + sRed reads done before counter bump / next stage
            if (tid == 0) {
                __threadfence();
                atomicAdd(&g_hcnt[myQ*32], 1u);
            }
        }
        // no grid barrier: A(t+1) consumes x first, h gated by g_hcnt
    }
}

extern "C" void kernel_launch(void* const* d_in, const int* in_sizes, int n_in,
                              void* d_out, int out_size) {
    const float* x     = (const float*)d_in[0];
    const float* Wa    = (const float*)d_in[1];
    const float* ba    = (const float*)d_in[2];
    const float* Wb    = (const float*)d_in[3];
    const float* bbv   = (const float*)d_in[4];
    const float* gamma = (const float*)d_in[5];
    const float* beta  = (const float*)d_in[6];
    float* out = (float*)d_out;

    cudaFuncSetAttribute(rnn_kernel, cudaFuncAttributeMaxDynamicSharedMemorySize, SMEM_BYTES);
    rnn_kernel<<<NBLK, NTHR, SMEM_BYTES>>>(x, Wa, ba, Wb, bbv, gamma, beta, out);
}

// round 17
// speedup vs baseline: 1.7745x; 1.7745x over previous
#include <cuda_runtime.h>
#include <cuda_bf16.h>
#include <math.h>
#include <stdint.h>

typedef uint32_t u32;

#define NBLK 128
#define NTHR 544            // 16 compute warps + 1 producer warp
#define BB   32
#define CC   1024
#define C2   2048
#define TT   1024
#define WS   2056   // weight row stride (bf16 elems): conflict-free LDSM

// SMEM byte layout: weights | 2x16KB act buffers | mbarriers
#define OFF_BUF_BYTES (48*WS*2)              // 197376 (128B aligned)
#define BUFSZ 16384
#define OFF_MBAR (OFF_BUF_BYTES + 2*BUFSZ)   // 230144
#define SMEM_BYTES (OFF_MBAR + 64)           // 230208

// GMEM staging (chunk-major, swizzled, [hi 8KB | lo 8KB] per 16KB chunk)
__device__ __align__(128) unsigned char g_xs[134217728]; // [t][8 chunks][16KB]
__device__ __align__(128) unsigned char g_hs[131072];    // [8 chunks][16KB]
__device__ __align__(128) unsigned char g_ys[262144];    // [16 chunks][16KB]
__device__ float g_y2[BB*CC];

// hierarchical grid barrier state (monotonic; replay-safe)
__device__ unsigned g_c1[8*32];
__device__ unsigned g_c2;
__device__ volatile unsigned g_gen;

__device__ __forceinline__ float geluf(float u) {
    return 0.5f * u * (1.0f + erff(u * 0.70710678118654752440f));
}

// two-level grid barrier: 8 group counters (16 CTAs each) -> 1 master (8 groups)
__device__ __forceinline__ void gbar(int cta) {
    __syncthreads();
    if (threadIdx.x == 0) {
        __threadfence();
        unsigned gen = g_gen;
        unsigned o = atomicAdd(&g_c1[(cta & 7) * 32], 1u);
        if ((o & 15u) == 15u) {
            unsigned o2 = atomicAdd(&g_c2, 1u);
            if ((o2 & 7u) == 7u) {
                __threadfence();
                g_gen = gen + 1u;
            } else {
                while (g_gen == gen) {}
            }
        } else {
            while (g_gen == gen) {}
        }
        __threadfence();
    }
    __syncthreads();
}

__device__ __forceinline__ void ldsm4(u32 (&r)[4], u32 addr) {
    asm volatile("ldmatrix.sync.aligned.m8n8.x4.shared.b16 {%0,%1,%2,%3}, [%4];"
        : "=r"(r[0]), "=r"(r[1]), "=r"(r[2]), "=r"(r[3]) : "r"(addr));
}
__device__ __forceinline__ void ldsm2(u32 (&r)[2], u32 addr) {
    asm volatile("ldmatrix.sync.aligned.m8n8.x2.shared.b16 {%0,%1}, [%2];"
        : "=r"(r[0]), "=r"(r[1]) : "r"(addr));
}
__device__ __forceinline__ void mma16816(float (&c)[4], const u32 (&a)[4], const u32 (&b)[2]) {
    asm volatile("mma.sync.aligned.m16n8k16.row.col.f32.bf16.bf16.f32 "
        "{%0,%1,%2,%3}, {%4,%5,%6,%7}, {%8,%9}, {%0,%1,%2,%3};"
        : "+f"(c[0]), "+f"(c[1]), "+f"(c[2]), "+f"(c[3])
        : "r"(a[0]), "r"(a[1]), "r"(a[2]), "r"(a[3]), "r"(b[0]), "r"(b[1]));
}

__device__ __forceinline__ void mbar_init(u32 a, u32 cnt) {
    asm volatile("mbarrier.init.shared.b64 [%0], %1;" :: "r"(a), "r"(cnt) : "memory");
}
__device__ __forceinline__ void mbar_arrive(u32 a) {
    asm volatile("mbarrier.arrive.shared.b64 _, [%0];" :: "r"(a) : "memory");
}
__device__ __forceinline__ void mbar_expect_tx(u32 a, u32 n) {
    asm volatile("mbarrier.arrive.expect_tx.shared.b64 _, [%0], %1;" :: "r"(a), "r"(n) : "memory");
}
__device__ __forceinline__ void mbar_wait(u32 a, u32 ph) {
    u32 done;
    asm volatile("{\n\t.reg .pred p;\n\t"
        "mbarrier.try_wait.parity.acquire.cta.shared::cta.b64 p, [%1], %2;\n\t"
        "selp.b32 %0, 1, 0, p;\n\t}"
        : "=r"(done) : "r"(a), "r"(ph) : "memory");
    if (!done) {
        asm volatile("{\n\t.reg .pred P1;\n\t"
            "WAIT_LOOP_%=:\n\t"
            "mbarrier.try_wait.parity.acquire.cta.shared::cta.b64 P1, [%0], %1, 0x989680;\n\t"
            "@P1 bra.uni WAIT_DONE_%=;\n\t"
            "bra.uni WAIT_LOOP_%=;\n\t"
            "WAIT_DONE_%=:\n\t}"
            :: "r"(a), "r"(ph) : "memory");
    }
}
__device__ __forceinline__ void bulk_cp(u32 dst, const void* src, u32 bytes, u32 mbar) {
    asm volatile("cp.async.bulk.shared::cluster.global.mbarrier::complete_tx::bytes "
        "[%0], [%1], %2, [%3];" :: "r"(dst), "l"(src), "r"(bytes), "r"(mbar) : "memory");
}
__device__ __forceinline__ void fence_async() {
    asm volatile("fence.proxy.async.shared::cta;" ::: "memory");
}
__device__ __forceinline__ void l2pf(const void* p) {
    asm volatile("prefetch.global.L2 [%0];" :: "l"(p));
}

__device__ __forceinline__ void split2(float v, __nv_bfloat16& h, __nv_bfloat16& l) {
    h = __float2bfloat16_rn(v);
    l = __float2bfloat16_rn(v - __bfloat162float(h));
}
__device__ __forceinline__ u32 packhl(__nv_bfloat16 a, __nv_bfloat16 b) {
    __nv_bfloat162 p = {a, b};
    return *(u32*)&p;
}

// swizzled byte offset within an 8KB plane (32 rows x 128 bf16 cols)
__device__ __forceinline__ u32 swz(u32 r, u32 c) {
    u32 b = (((r >> 3) + ((c >> 6) << 2)) << 10) + ((r & 7) << 7) + ((c & 63) << 1);
    return b ^ ((b >> 3) & 0x70);
}

__global__ void __launch_bounds__(NTHR, 1)
rnn_kernel(const float* __restrict__ x,   const float* __restrict__ Wa,
           const float* __restrict__ ba,  const float* __restrict__ Wb,
           const float* __restrict__ bbv, const float* __restrict__ gamma,
           const float* __restrict__ beta, float* __restrict__ out)
{
    extern __shared__ unsigned char smb[];
    __nv_bfloat16* sWaHi = (__nv_bfloat16*)(smb);
    __nv_bfloat16* sWaLo = (__nv_bfloat16*)(smb + 16*WS*2);
    __nv_bfloat16* sWbHi = (__nv_bfloat16*)(smb + 32*WS*2);
    __nv_bfloat16* sWbLo = (__nv_bfloat16*)(smb + 40*WS*2);
    float* sRed = (float*)(smb + OFF_BUF_BYTES);   // aliases buffers; epilogue-only

    const int tid = threadIdx.x;
    const int cta = blockIdx.x;
    const int lane = tid & 31, wid = tid >> 5;

    const u32 smemBase = (u32)__cvta_generic_to_shared(smb);
    const u32 mbFull[2]  = {smemBase + OFF_MBAR,      smemBase + OFF_MBAR + 8};
    const u32 mbEmpty[2] = {smemBase + OFF_MBAR + 16, smemBase + OFF_MBAR + 24};
    const u32 bufB[2]    = {smemBase + OFF_BUF_BYTES, smemBase + OFF_BUF_BYTES + BUFSZ};

    if (tid == 0) {
        mbar_init(mbFull[0], 1);  mbar_init(mbFull[1], 1);
        mbar_init(mbEmpty[0], 16); mbar_init(mbEmpty[1], 16);
    }

    // ---- one-time: weights -> smem bf16 hi/lo planes ----
    for (int idx = tid; idx < 16*C2; idx += NTHR) {
        int r = idx >> 11, k = idx & (C2-1);
        float v = Wa[(size_t)(cta*16 + r)*C2 + k];
        split2(v, sWaHi[r*WS + k], sWaLo[r*WS + k]);
    }
    for (int idx = tid; idx < 8*C2; idx += NTHR) {
        int r = idx >> 11, k = idx & (C2-1);
        float v = Wb[(size_t)(cta*8 + r)*C2 + k];
        split2(v, sWbHi[r*WS + k], sWbLo[r*WS + k]);
    }
    // ---- one-time: x -> chunk-major swizzled hi/lo (this CTA owns 8 t values) ----
    for (int tt = cta*8; tt < cta*8 + 8; ++tt) {
        for (int p = tid; p < 32*512; p += NTHR) {
            int b = p >> 9, c0 = (p & 511) << 1;
            float2 v = *(const float2*)(x + ((size_t)b*TT + tt)*CC + c0);
            __nv_bfloat16 h0,l0,h1,l1;
            split2(v.x, h0, l0);
            split2(v.y, h1, l1);
            unsigned char* base = g_xs + ((size_t)tt*8 + (c0 >> 7))*BUFSZ;
            u32 off = swz((u32)b, (u32)(c0 & 127));
            *(u32*)(base + off)        = packhl(h0, h1);
            *(u32*)(base + 8192 + off) = packhl(l0, l1);
        }
    }
    // ---- h0 = 0 ----
    {
        int g = cta*NTHR + tid;
        if (g < 32768) ((u32*)g_hs)[g] = 0u;
    }
    gbar(cta);

    // ---- warp roles (compute warps 0-15; warp 16 = producer) ----
    const int kspA = wid & 3, nt = wid >> 2;   // A: 4 n-tiles(8b) x 4-way k-split
    const int mtB = wid & 1, kspB = wid >> 1;  // B: 2 m-tiles(16b) x 8-way k-split
    const int myB = cta >> 2, myQ = cta & 3;

    const int aRow = lane & 15, aKh = (lane >> 4) * 8;
    const int bRow = lane & 7,  bKh = ((lane >> 3) & 1) * 8;
    const u32 waHi = smemBase + 0        + (aRow*WS + aKh)*2;
    const u32 waLo = smemBase + 16*WS*2  + (aRow*WS + aKh)*2;
    const u32 wbHi = smemBase + 32*WS*2  + (bRow*WS + bKh)*2;
    const u32 wbLo = smemBase + 40*WS*2  + (bRow*WS + bKh)*2;

    u32 aAct[2][2], bAct[2];
    #pragma unroll
    for (int s = 0; s < 2; ++s) {
        #pragma unroll
        for (int u = 0; u < 2; ++u)
            aAct[s][u] = bufB[s] + swz((u32)((nt & 3)*8 + (lane & 7)),
                                       (u32)(32*(kspA) + 16*u + ((lane >> 3) & 1)*8));
        bAct[s] = bufB[s] + swz((u32)((mtB)*16 + (lane & 15)),
                                (u32)(16*(kspB & 7) + ((lane >> 4) & 1)*8));
    }

    int cPh[2] = {0, 0};     // consumer full-parity
    int pPh[2] = {0, 0};     // producer empty-parity
    int pFirst[2] = {1, 1};  // skip empty-wait on first-ever use

    for (int t = 0; t < TT; ++t) {
        // ===== Phase A: y = gelu([h,x_t] @ Wa^T + ba) =====
        float c0a[4] = {0,0,0,0}, c1a[4] = {0,0,0,0}, c2a[4] = {0,0,0,0};
        if (wid < 16) {
            #pragma unroll 2
            for (int ch = 0; ch < 16; ++ch) {
                const int s = ch & 1;
                mbar_wait(mbFull[s], cPh[s]); cPh[s] ^= 1;
                #pragma unroll
                for (int u = 0; u < 2; ++u) {
                    const int kb = ch*128 + 32*kspA + 16*u;
                    u32 Ah[4], Al[4], Bh[2], Bl[2];
                    ldsm4(Ah, waHi + kb*2);
                    ldsm4(Al, waLo + kb*2);
                    ldsm2(Bh, aAct[s][u]);
                    ldsm2(Bl, aAct[s][u] + 8192);
                    mma16816(c0a, Ah, Bh);
                    mma16816(c1a, Ah, Bl);
                    mma16816(c2a, Al, Bh);
                }
                __syncwarp();
                if (lane == 0) mbar_arrive(mbEmpty[s]);
            }
        } else if (lane == 0) {
            fence_async();
            for (int ch = 0; ch < 16; ++ch) {
                const int s = ch & 1;
                if (pFirst[s]) pFirst[s] = 0;
                else { mbar_wait(mbEmpty[s], pPh[s]); pPh[s] ^= 1; }
                const void* src = (ch < 8)
                    ? (const void*)(g_hs + (size_t)ch*BUFSZ)
                    : (const void*)(g_xs + ((size_t)t*8 + (ch - 8))*BUFSZ);
                mbar_expect_tx(mbFull[s], BUFSZ);
                bulk_cp(bufB[s], src, BUFSZ, mbFull[s]);
            }
        }
        {   // A epilogue: partials -> sRed[kspA][16j][32b] (stride 34)
            __syncthreads();   // all warps done with buffers before sRed (aliases buf0)
            if (wid < 16) {
                const int r0 = lane >> 2, cb = nt*8 + 2*(lane & 3);
                *(float2*)(sRed + (kspA*16 + r0    )*34 + cb) = make_float2(c0a[0]+c1a[0]+c2a[0], c0a[1]+c1a[1]+c2a[1]);
                *(float2*)(sRed + (kspA*16 + r0 + 8)*34 + cb) = make_float2(c0a[2]+c1a[2]+c2a[2], c0a[3]+c1a[3]+c2a[3]);
            }
            __syncthreads();
            if (tid < 256) {
                const int b = tid >> 3, j2 = (tid & 7)*2;
                const int jg0 = cta*16 + j2;
                float v0 = sRed[j2*34 + b] + sRed[(16 + j2)*34 + b]
                         + sRed[(32 + j2)*34 + b] + sRed[(48 + j2)*34 + b];
                float v1 = sRed[(j2+1)*34 + b] + sRed[(16 + j2+1)*34 + b]
                         + sRed[(32 + j2+1)*34 + b] + sRed[(48 + j2+1)*34 + b];
                float y0 = geluf(v0 + __ldg(ba + jg0));
                float y1 = geluf(v1 + __ldg(ba + jg0 + 1));
                __nv_bfloat16 h0,l0,h1,l1;
                split2(y0, h0, l0);
                split2(y1, h1, l1);
                unsigned char* base = g_ys + (size_t)(jg0 >> 7)*BUFSZ;
                u32 off = swz((u32)b, (u32)(jg0 & 127));
                *(u32*)(base + off)        = packhl(h0, h1);
                *(u32*)(base + 8192 + off) = packhl(l0, l1);
            }
        }
        gbar(cta);

        // ===== Phase B: y2 = y @ Wb^T + bb =====
        float d0[4] = {0,0,0,0}, d1[4] = {0,0,0,0}, d2[4] = {0,0,0,0};
        if (wid < 16) {
            #pragma unroll 2
            for (int ch = 0; ch < 16; ++ch) {
                const int s = ch & 1;
                mbar_wait(mbFull[s], cPh[s]); cPh[s] ^= 1;
                {
                    const int kb = ch*128 + 16*kspB;
                    u32 Ah[4], Al[4], Bh[2], Bl[2];
                    ldsm4(Ah, bAct[s]);
                    ldsm4(Al, bAct[s] + 8192);
                    ldsm2(Bh, wbHi + kb*2);
                    ldsm2(Bl, wbLo + kb*2);
                    mma16816(d0, Ah, Bh);
                    mma16816(d1, Ah, Bl);
                    mma16816(d2, Al, Bh);
                }
                __syncwarp();
                if (lane == 0) mbar_arrive(mbEmpty[s]);
            }
        } else if (lane == 0) {
            fence_async();
            for (int ch = 0; ch < 16; ++ch) {
                const int s = ch & 1;
                mbar_wait(mbEmpty[s], pPh[s]); pPh[s] ^= 1;
                mbar_expect_tx(mbFull[s], BUFSZ);
                bulk_cp(bufB[s], g_ys + (size_t)ch*BUFSZ, BUFSZ, mbFull[s]);
            }
        }
        {   // B epilogue: partials -> sRed[kspB][32b][8j] (stride 10)
            __syncthreads();
            if (wid < 16) {
                const int r0 = mtB*16 + (lane >> 2), cb = 2*(lane & 3);
                *(float2*)(sRed + (kspB*32 + r0    )*10 + cb) = make_float2(d0[0]+d1[0]+d2[0], d0[1]+d1[1]+d2[1]);
                *(float2*)(sRed + (kspB*32 + r0 + 8)*10 + cb) = make_float2(d0[2]+d1[2]+d2[2], d0[3]+d1[3]+d2[3]);
            }
            __syncthreads();
            if (tid < 256) {
                const int b = tid >> 3, j = tid & 7;
                float v = 0.f;
                #pragma unroll
                for (int p = 0; p < 8; ++p) v += sRed[(p*32 + b)*10 + j];
                const int jg = cta*8 + j;
                v += __ldg(bbv + jg);
                __stcg(&g_y2[(size_t)b*CC + jg], v);
            }
        }
        gbar(cta);

        // ===== Phase C: h = LN(y2)+y2  (+ L2-prefetch next x) =====
        {
            if (cta < 8 && t + 1 < TT && tid < 128)
                l2pf(g_xs + ((size_t)(t + 1)*8 + cta)*BUFSZ + (size_t)tid*128);

            float s = 0.f, sq = 0.f;
            #pragma unroll
            for (int i = tid; i < CC; i += NTHR) {
                float v = __ldcg(g_y2 + (size_t)myB*CC + i);
                s += v; sq += v*v;
            }
            #pragma unroll
            for (int o = 16; o; o >>= 1) {
                s  += __shfl_xor_sync(0xffffffffu, s,  o);
                sq += __shfl_xor_sync(0xffffffffu, sq, o);
            }
            if (lane == 0) { sRed[wid] = s; sRed[20 + wid] = sq; }
            __syncthreads();
            if (tid < 128) {
                float S = 0.f, Q = 0.f;
                #pragma unroll
                for (int w = 0; w < 17; ++w) { S += sRed[w]; Q += sRed[20 + w]; }
                float mu  = S * (1.0f / CC);
                float var = Q * (1.0f / CC) - mu * mu;
                float r   = rsqrtf(var + 1e-5f);
                int c0 = myQ * 256 + tid*2;
                float v0 = __ldcg(g_y2 + (size_t)myB*CC + c0);
                float v1 = __ldcg(g_y2 + (size_t)myB*CC + c0 + 1);
                float hn0 = (v0 - mu) * r * __ldg(gamma + c0)     + __ldg(beta + c0)     + v0;
                float hn1 = (v1 - mu) * r * __ldg(gamma + c0 + 1) + __ldg(beta + c0 + 1) + v1;
                *(float2*)(out + (size_t)myB*TT*CC + (size_t)t*CC + c0) = make_float2(hn0, hn1);
                __nv_bfloat16 h0,l0,h1,l1;
                split2(hn0, h0, l0);
                split2(hn1, h1, l1);
                unsigned char* base = g_hs + (size_t)(c0 >> 7)*BUFSZ;
                u32 off = swz((u32)myB, (u32)(c0 & 127));
                *(u32*)(base + off)        = packhl(h0, h1);
                *(u32*)(base + 8192 + off) = packhl(l0, l1);
            }
        }
        gbar(cta);
    }
}

extern "C" void kernel_launch(void* const* d_in, const int* in_sizes, int n_in,
                              void* d_out, int out_size) {
    const float* x     = (const float*)d_in[0];
    const float* Wa    = (const float*)d_in[1];
    const float* ba    = (const float*)d_in[2];
    const float* Wb    = (const float*)d_in[3];
    const float* bbv   = (const float*)d_in[4];
    const float* gamma = (const float*)d_in[5];
    const float* beta  = (const float*)d_in[6];
    float* out = (float*)d_out;

    cudaFuncSetAttribute(rnn_kernel, cudaFuncAttributeMaxDynamicSharedMemorySize, SMEM_BYTES);
    rnn_kernel<<<NBLK, NTHR, SMEM_BYTES>>>(x, Wa, ba, Wb, bbv, gamma, beta, out);
}